// round 3
// baseline (speedup 1.0000x reference)
#include <cuda_runtime.h>
#include <math.h>

#define NN 256
#define TT 1000
#define NO_ 10
#define NS_ 10
#define DD 20      // NO_ + NS_
#define HH 64
#define GG 192     // 3*HH
#define SPB 2      // samples per block

// Scratch: GRU hidden states [N, T, H]  (65.5 MB) — static device array (no allocs allowed)
__device__ float g_hs[(size_t)NN * TT * HH];
__device__ double g_acc;

__global__ void zero_acc_kernel() { g_acc = 0.0; }

// ---------------------------------------------------------------------------
// GRU scan: 128 blocks x 192 threads, each block owns 2 samples, loops all T.
// Thread k holds column k of Wi (20 floats) and Wh (64 floats) in registers.
// Shared memory holds h (broadcast), x (broadcast), and the xp/hp exchange.
// ---------------------------------------------------------------------------
__global__ void __launch_bounds__(GG, 1) gru_scan_kernel(
    const float* __restrict__ Yi, const float* __restrict__ Xh,
    const float* __restrict__ Wi, const float* __restrict__ Wh,
    const float* __restrict__ bi, const float* __restrict__ bh)
{
    __shared__ float sh_h[SPB][HH];
    __shared__ float sh_x[SPB][DD];
    __shared__ float sh_xp[SPB][GG];
    __shared__ float sh_hp[SPB][GG];

    const int k  = threadIdx.x;
    const int n0 = blockIdx.x * SPB;

    // weights for this output column, coalesced loads
    float wi[DD], wh[HH];
#pragma unroll
    for (int d = 0; d < DD; d++) wi[d] = Wi[d * GG + k];
#pragma unroll
    for (int j = 0; j < HH; j++) wh[j] = Wh[j * GG + k];
    const float bik = bi[k];
    const float bhk = bh[k];

    if (k < SPB * HH) sh_h[k >> 6][k & 63] = 0.0f;   // h0 = 0

    // x loader role: threads 0..39 each own one (sample, feature) slot
    const int ls = k / DD;
    const int lj = k - ls * DD;
    float xreg = 0.0f;
    if (k < SPB * DD) {
        const int n = n0 + ls;
        xreg = (lj < NO_) ? Yi[((size_t)n * TT) * NO_ + lj]
                          : Xh[((size_t)n * TT) * NS_ + (lj - NO_)];
    }

    for (int t = 0; t < TT; t++) {
        if (k < SPB * DD) sh_x[ls][lj] = xreg;
        __syncthreads();   // also orders previous step's sh_h writes
        // prefetch next step's x (hidden behind the compute below)
        if (k < SPB * DD && t + 1 < TT) {
            const int n = n0 + ls;
            xreg = (lj < NO_) ? Yi[((size_t)n * TT + t + 1) * NO_ + lj]
                              : Xh[((size_t)n * TT + t + 1) * NS_ + (lj - NO_)];
        }

#pragma unroll
        for (int s = 0; s < SPB; s++) {
            float ax = bik;
            const float4* x4 = (const float4*)sh_x[s];
#pragma unroll
            for (int q = 0; q < DD / 4; q++) {
                float4 v = x4[q];
                ax = fmaf(v.x, wi[4 * q + 0], ax);
                ax = fmaf(v.y, wi[4 * q + 1], ax);
                ax = fmaf(v.z, wi[4 * q + 2], ax);
                ax = fmaf(v.w, wi[4 * q + 3], ax);
            }
            float ah = bhk;
            const float4* h4 = (const float4*)sh_h[s];
#pragma unroll
            for (int q = 0; q < HH / 4; q++) {
                float4 v = h4[q];
                ah = fmaf(v.x, wh[4 * q + 0], ah);
                ah = fmaf(v.y, wh[4 * q + 1], ah);
                ah = fmaf(v.z, wh[4 * q + 2], ah);
                ah = fmaf(v.w, wh[4 * q + 3], ah);
            }
            sh_xp[s][k] = ax;
            sh_hp[s][k] = ah;
        }
        __syncthreads();

        // gates: 128 threads, one per (sample, hidden unit)
        if (k < SPB * HH) {
            const int s = k >> 6, i = k & 63;
            const float xr = sh_xp[s][i],          hr = sh_hp[s][i];
            const float xz = sh_xp[s][HH + i],     hz = sh_hp[s][HH + i];
            const float xn = sh_xp[s][2 * HH + i], hn = sh_hp[s][2 * HH + i];
            const float r  = 1.0f / (1.0f + expf(-(xr + hr)));
            const float z  = 1.0f / (1.0f + expf(-(xz + hz)));
            const float nn = tanhf(xn + r * hn);
            const float hold = sh_h[s][i];
            const float hnew = (1.0f - z) * nn + z * hold;
            sh_h[s][i] = hnew;
            g_hs[((size_t)(n0 + s) * TT + t) * HH + i] = hnew;
        }
    }
}

// ---------------------------------------------------------------------------
// Likelihood: one thread per (n, t). Heads + 10x10 SPD build + packed-lower
// Cholesky + forward solve, all in registers; block reduce to one atomicAdd.
// ---------------------------------------------------------------------------
__global__ void __launch_bounds__(256) lik_kernel(
    const float* __restrict__ Yi, const float* __restrict__ Cw,
    const float* __restrict__ Hm, const float* __restrict__ mu_w,
    const float* __restrict__ W_mu, const float* __restrict__ b_mu,
    const float* __restrict__ W_var, const float* __restrict__ b_var)
{
    __shared__ float2 sWmv[HH * NS_];          // (W_mu, W_var) interleaved
    __shared__ float  sH[NO_ * NS_];
    __shared__ float  sbm[NS_], sbv[NS_], smw[NO_];
    __shared__ double wsum[8];

    const int tid = threadIdx.x;
    for (int i = tid; i < HH * NS_; i += blockDim.x)
        sWmv[i] = make_float2(W_mu[i], W_var[i]);
    if (tid < NO_ * NS_) sH[tid] = Hm[tid];
    if (tid < NS_) { sbm[tid] = b_mu[tid]; sbv[tid] = b_var[tid]; }
    if (tid < NO_) smw[tid] = mu_w[tid];
    __syncthreads();

    const int idx = blockIdx.x * blockDim.x + tid;
    double local = 0.0;
    if (idx < NN * TT) {
        const int n = idx / TT;
        const int t = idx - n * TT;

        float mu[NS_], vr[NS_];
#pragma unroll
        for (int j = 0; j < NS_; j++) { mu[j] = sbm[j]; vr[j] = sbv[j]; }

        const float* hp = g_hs + ((size_t)n * TT + t) * HH;
#pragma unroll
        for (int q = 0; q < HH / 4; q++) {
            const float4 hv = ((const float4*)hp)[q];
            const float hl[4] = {hv.x, hv.y, hv.z, hv.w};
#pragma unroll
            for (int l = 0; l < 4; l++) {
                const float h = hl[l];
                const int base = (4 * q + l) * NS_;
#pragma unroll
                for (int j = 0; j < NS_; j++) {
                    const float2 w = sWmv[base + j];
                    mu[j] = fmaf(h, w.x, mu[j]);
                    vr[j] = fmaf(h, w.y, vr[j]);
                }
            }
        }

        float var[NS_];
#pragma unroll
        for (int j = 0; j < NS_; j++) {
            const float x = vr[j];
            var[j] = (x > 15.0f) ? x : log1pf(expf(x));   // softplus
        }

        // residual e = y - (H mu + mu_w)
        float e[NO_];
#pragma unroll
        for (int i = 0; i < NO_; i++) {
            float m = smw[i];
#pragma unroll
            for (int j = 0; j < NS_; j++) m = fmaf(sH[i * NS_ + j], mu[j], m);
            e[i] = Yi[((size_t)n * TT + t) * NO_ + i] - m;
        }

        // A = H diag(var) H^T + Cw, packed lower triangle
        float A[NO_ * (NO_ + 1) / 2];
        const float* cw = Cw + (size_t)n * NO_ * NO_;
#pragma unroll
        for (int i = 0; i < NO_; i++)
#pragma unroll
            for (int kk = 0; kk <= i; kk++)
                A[i * (i + 1) / 2 + kk] = cw[i * NO_ + kk];
#pragma unroll
        for (int j = 0; j < NS_; j++) {
            const float vj = var[j];
            float hj[NO_];
#pragma unroll
            for (int i = 0; i < NO_; i++) hj[i] = sH[i * NS_ + j];
#pragma unroll
            for (int i = 0; i < NO_; i++) {
                const float hv = hj[i] * vj;
#pragma unroll
                for (int kk = 0; kk <= i; kk++)
                    A[i * (i + 1) / 2 + kk] = fmaf(hv, hj[kk], A[i * (i + 1) / 2 + kk]);
            }
        }

        // in-place packed Cholesky
        float rdi[NO_];
        float logdet = 0.0f;
#pragma unroll
        for (int i = 0; i < NO_; i++) {
#pragma unroll
            for (int kk = 0; kk < i; kk++) {
                float s = A[i * (i + 1) / 2 + kk];
#pragma unroll
                for (int j2 = 0; j2 < NO_; j2++)
                    if (j2 < kk)
                        s -= A[i * (i + 1) / 2 + j2] * A[kk * (kk + 1) / 2 + j2];
                A[i * (i + 1) / 2 + kk] = s * rdi[kk];
            }
            float s = A[i * (i + 1) / 2 + i];
#pragma unroll
            for (int j2 = 0; j2 < NO_; j2++)
                if (j2 < i) {
                    const float l = A[i * (i + 1) / 2 + j2];
                    s -= l * l;
                }
            const float Lii = sqrtf(s);
            rdi[i] = 1.0f / Lii;
            logdet += logf(Lii);
        }
        logdet *= 2.0f;

        // forward solve z = L^{-1} e ;  quad = |z|^2
        float quad = 0.0f;
        float zv[NO_];
#pragma unroll
        for (int i = 0; i < NO_; i++) {
            float s = e[i];
#pragma unroll
            for (int j2 = 0; j2 < NO_; j2++)
                if (j2 < i) s -= A[i * (i + 1) / 2 + j2] * zv[j2];
            zv[i] = s * rdi[i];
            quad = fmaf(zv[i], zv[i], quad);
        }

        local = (double)(logdet + quad);
    }

    // block reduction -> one atomicAdd
    for (int off = 16; off > 0; off >>= 1)
        local += __shfl_down_sync(0xffffffffu, local, off);
    if ((tid & 31) == 0) wsum[tid >> 5] = local;
    __syncthreads();
    if (tid == 0) {
        double s = 0.0;
#pragma unroll
        for (int w = 0; w < 8; w++) s += wsum[w];
        atomicAdd(&g_acc, s);
    }
}

__global__ void finalize_kernel(float* out) {
    const double LOG2PI = 1.8378770664093453;
    out[0] = (float)(-0.5 * LOG2PI - 0.5 * g_acc / ((double)NN * TT * NO_));
}

extern "C" void kernel_launch(void* const* d_in, const int* in_sizes, int n_in,
                              void* d_out, int out_size)
{
    const float* Yi    = (const float*)d_in[0];
    const float* Xh    = (const float*)d_in[1];
    const float* Cw    = (const float*)d_in[2];
    const float* Hm    = (const float*)d_in[3];
    const float* mu_w  = (const float*)d_in[4];
    const float* Wi    = (const float*)d_in[5];
    const float* Wh    = (const float*)d_in[6];
    const float* bi    = (const float*)d_in[7];
    const float* bh    = (const float*)d_in[8];
    const float* W_mu  = (const float*)d_in[9];
    const float* b_mu  = (const float*)d_in[10];
    const float* W_var = (const float*)d_in[11];
    const float* b_var = (const float*)d_in[12];
    float* out = (float*)d_out;

    zero_acc_kernel<<<1, 1>>>();
    gru_scan_kernel<<<NN / SPB, GG>>>(Yi, Xh, Wi, Wh, bi, bh);
    lik_kernel<<<(NN * TT + 255) / 256, 256>>>(Yi, Cw, Hm, mu_w, W_mu, b_mu, W_var, b_var);
    finalize_kernel<<<1, 1>>>(out);
}

// round 6
// speedup vs baseline: 1.2442x; 1.2442x over previous
#include <cuda_runtime.h>
#include <math.h>

#define NN 256
#define TT 1000
#define NO_ 10
#define NS_ 10
#define DD 20      // NO_ + NS_
#define HH 64
#define GG 192     // 3*HH
#define RPB 16     // rows per block in xproj

typedef unsigned long long ull;

// Scratch (no allocations allowed): hidden states + precomputed input projections
__device__ float g_hs[(size_t)NN * TT * HH];   // 65.5 MB
__device__ float g_xp[(size_t)NN * TT * GG];   // 196.6 MB
__device__ double g_acc;
__device__ unsigned int g_done;

// ---- packed f32x2 helpers (Blackwell sm_103a) ------------------------------
__device__ __forceinline__ ull pack2(float lo, float hi) {
    ull r; asm("mov.b64 %0,{%1,%2};" : "=l"(r) : "f"(lo), "f"(hi)); return r;
}
__device__ __forceinline__ float2 unpack2(ull v) {
    float lo, hi; asm("mov.b64 {%0,%1},%2;" : "=f"(lo), "=f"(hi) : "l"(v));
    return make_float2(lo, hi);
}
__device__ __forceinline__ ull fma2(ull a, ull b, ull c) {
    ull d; asm("fma.rn.f32x2 %0,%1,%2,%3;" : "=l"(d) : "l"(a), "l"(b), "l"(c)); return d;
}
__device__ __forceinline__ ull add2(ull a, ull b) {
    ull d; asm("add.rn.f32x2 %0,%1,%2;" : "=l"(d) : "l"(a), "l"(b)); return d;
}
__device__ __forceinline__ float tanh_fast(float x) {
    float y; asm("tanh.approx.f32 %0,%1;" : "=f"(y) : "f"(x)); return y;
}
__device__ __forceinline__ float sigmoid_fast(float x) {
    return fmaf(0.5f, tanh_fast(0.5f * x), 0.5f);
}

// ---------------------------------------------------------------------------
// xproj: xp[n,t,k] = bi[k] + sum_d x[n,t,d] * Wi[d,k]   (fully parallel)
// 16000 blocks x 192 threads, 16 rows/block, FFMA2 throughput-bound.
// ---------------------------------------------------------------------------
__global__ void __launch_bounds__(GG) xproj_kernel(
    const float* __restrict__ Yi, const float* __restrict__ Xh,
    const float* __restrict__ Wi, const float* __restrict__ bi)
{
    __shared__ __align__(16) float sx[RPB][DD];
    const int k = threadIdx.x;
    if (blockIdx.x == 0 && k == 0) { g_acc = 0.0; g_done = 0u; }

    ull wi2[DD / 2];
#pragma unroll
    for (int p = 0; p < DD / 2; p++)
        wi2[p] = pack2(Wi[(2 * p) * GG + k], Wi[(2 * p + 1) * GG + k]);
    const float bik = bi[k];

    const size_t row0 = (size_t)blockIdx.x * RPB;
    for (int i = k; i < RPB * DD; i += GG) {
        const int r = i / DD, d = i - r * DD;
        sx[r][d] = (d < NO_) ? Yi[(row0 + r) * NO_ + d]
                             : Xh[(row0 + r) * NS_ + (d - NO_)];
    }
    __syncthreads();

#pragma unroll 4
    for (int r = 0; r < RPB; r++) {
        const ull* x2 = (const ull*)sx[r];
        ull a0 = pack2(bik, 0.0f), a1 = pack2(0.0f, 0.0f);
#pragma unroll
        for (int p = 0; p < DD / 2; p += 2) {
            a0 = fma2(x2[p],     wi2[p],     a0);
            a1 = fma2(x2[p + 1], wi2[p + 1], a1);
        }
        const float2 f = unpack2(add2(a0, a1));
        g_xp[(row0 + r) * GG + k] = f.x + f.y;
    }
}

// ---------------------------------------------------------------------------
// GRU scan: 256 blocks x 192 threads (1 sample/block, 2 blocks/SM).
// Thread k holds Wh column k as 32 packed f32x2 pairs; h broadcast via shared.
// xp streamed from gmem with 2-deep prefetch.
// ---------------------------------------------------------------------------
__global__ void __launch_bounds__(GG, 2) gru_scan_kernel(
    const float* __restrict__ Wh, const float* __restrict__ bh)
{
    __shared__ __align__(16) float sh_h[HH];
    __shared__ float sh_g[GG];     // xp + h-projection (all 192 gate pre-acts)
    __shared__ float sh_hn[HH];    // h-projection only, n-gate columns

    const int k = threadIdx.x;
    const int n = blockIdx.x;

    ull wh2[HH / 2];
#pragma unroll
    for (int p = 0; p < HH / 2; p++)
        wh2[p] = pack2(Wh[(2 * p) * GG + k], Wh[(2 * p + 1) * GG + k]);
    const float bhk = bh[k];

    if (k < HH) sh_h[k] = 0.0f;

    const float* xp = g_xp + (size_t)n * TT * GG + k;
    float xp0 = xp[0];
    float xp1 = xp[GG];
    float* hs = g_hs + (size_t)n * TT * HH;
    __syncthreads();

    for (int t = 0; t < TT; t++) {
        // prefetch t+2 early — ~1.5 steps of slack vs DRAM latency
        const float xpn = (t + 2 < TT) ? xp[(size_t)(t + 2) * GG] : 0.0f;

        const ulonglong2* h4 = (const ulonglong2*)sh_h;
        ull a0 = pack2(bhk, 0.0f), a1 = pack2(0.0f, 0.0f);
#pragma unroll
        for (int q = 0; q < HH / 4; q++) {
            const ulonglong2 hv = h4[q];
            a0 = fma2(hv.x, wh2[2 * q],     a0);
            a1 = fma2(hv.y, wh2[2 * q + 1], a1);
        }
        const float2 f = unpack2(add2(a0, a1));
        const float ah = f.x + f.y;

        sh_g[k] = xp0 + ah;
        if (k >= 2 * HH) sh_hn[k - 2 * HH] = ah;
        xp0 = xp1;
        xp1 = xpn;
        __syncthreads();

        if (k < HH) {
            const float r  = sigmoid_fast(sh_g[k]);
            const float z  = sigmoid_fast(sh_g[HH + k]);
            const float hn = sh_hn[k];
            // xn + r*hn = (xn + hn) + (r-1)*hn
            const float nn = tanh_fast(fmaf(r - 1.0f, hn, sh_g[2 * HH + k]));
            const float hnew = fmaf(z, sh_h[k] - nn, nn);   // (1-z)n + z h
            sh_h[k] = hnew;
            hs[(size_t)t * HH + k] = hnew;
        }
        __syncthreads();
    }
}

// ---------------------------------------------------------------------------
// Likelihood: one thread per (n,t); FFMA2 heads, packed Cholesky in registers.
// Last block writes the final scalar (no separate finalize launch).
// ---------------------------------------------------------------------------
__global__ void __launch_bounds__(256) lik_kernel(
    const float* __restrict__ Yi, const float* __restrict__ Cw,
    const float* __restrict__ Hm, const float* __restrict__ mu_w,
    const float* __restrict__ W_mu, const float* __restrict__ b_mu,
    const float* __restrict__ W_var, const float* __restrict__ b_var,
    float* __restrict__ out)
{
    __shared__ ull sWm2[(HH / 2) * NS_];
    __shared__ ull sWv2[(HH / 2) * NS_];
    __shared__ float sH[NO_ * NS_], sbm[NS_], sbv[NS_], smw[NO_];
    __shared__ double wsum[8];
    __shared__ bool is_last;

    const int tid = threadIdx.x;
    for (int i = tid; i < (HH / 2) * NS_; i += 256) {
        const int p = i / NS_, j = i - p * NS_;
        sWm2[i] = pack2(W_mu[(2 * p) * NS_ + j],  W_mu[(2 * p + 1) * NS_ + j]);
        sWv2[i] = pack2(W_var[(2 * p) * NS_ + j], W_var[(2 * p + 1) * NS_ + j]);
    }
    if (tid < NO_ * NS_) sH[tid] = Hm[tid];
    if (tid < NS_) { sbm[tid] = b_mu[tid]; sbv[tid] = b_var[tid]; }
    if (tid < NO_) smw[tid] = mu_w[tid];
    if (tid == 0) is_last = false;
    __syncthreads();

    const int idx = blockIdx.x * 256 + tid;      // grid is exact: NN*TT/256
    const int n = idx / TT;

    // heads: mu = h@W_mu + b_mu ; vr = h@W_var + b_var   (packed f32x2)
    ull mu2[NS_], vr2[NS_];
#pragma unroll
    for (int j = 0; j < NS_; j++) { mu2[j] = 0ull; vr2[j] = 0ull; }

    const ulonglong2* h4 = (const ulonglong2*)(g_hs + (size_t)idx * HH);
#pragma unroll
    for (int q = 0; q < HH / 4; q++) {
        const ulonglong2 hv = h4[q];
        const int p0 = 2 * q;
#pragma unroll
        for (int j = 0; j < NS_; j++) {
            mu2[j] = fma2(hv.x, sWm2[p0 * NS_ + j], mu2[j]);
            vr2[j] = fma2(hv.x, sWv2[p0 * NS_ + j], vr2[j]);
        }
#pragma unroll
        for (int j = 0; j < NS_; j++) {
            mu2[j] = fma2(hv.y, sWm2[(p0 + 1) * NS_ + j], mu2[j]);
            vr2[j] = fma2(hv.y, sWv2[(p0 + 1) * NS_ + j], vr2[j]);
        }
    }

    float mu[NS_], var[NS_];
#pragma unroll
    for (int j = 0; j < NS_; j++) {
        const float2 m = unpack2(mu2[j]);
        mu[j] = sbm[j] + m.x + m.y;
        const float2 v = unpack2(vr2[j]);
        const float x = sbv[j] + v.x + v.y;
        var[j] = (x > 15.0f) ? x : __logf(1.0f + __expf(x));   // softplus
    }

    // residual e = y - (H mu + mu_w)
    float e[NO_];
#pragma unroll
    for (int i = 0; i < NO_; i++) {
        float m = smw[i];
#pragma unroll
        for (int j = 0; j < NS_; j++) m = fmaf(sH[i * NS_ + j], mu[j], m);
        e[i] = Yi[(size_t)idx * NO_ + i] - m;
    }

    // A = H diag(var) H^T + Cw, packed lower triangle
    float A[NO_ * (NO_ + 1) / 2];
    const float* cw = Cw + (size_t)n * NO_ * NO_;
#pragma unroll
    for (int i = 0; i < NO_; i++)
#pragma unroll
        for (int kk = 0; kk <= i; kk++)
            A[i * (i + 1) / 2 + kk] = cw[i * NO_ + kk];
#pragma unroll
    for (int j = 0; j < NS_; j++) {
        const float vj = var[j];
        float hj[NO_];
#pragma unroll
        for (int i = 0; i < NO_; i++) hj[i] = sH[i * NS_ + j];
#pragma unroll
        for (int i = 0; i < NO_; i++) {
            const float hv = hj[i] * vj;
#pragma unroll
            for (int kk = 0; kk <= i; kk++)
                A[i * (i + 1) / 2 + kk] = fmaf(hv, hj[kk], A[i * (i + 1) / 2 + kk]);
        }
    }

    // in-place packed Cholesky; logdet = sum log(s_i) since Lii^2 = s_i
    float rdi[NO_];
    float logdet = 0.0f;
#pragma unroll
    for (int i = 0; i < NO_; i++) {
#pragma unroll
        for (int kk = 0; kk < i; kk++) {
            float s = A[i * (i + 1) / 2 + kk];
#pragma unroll
            for (int j2 = 0; j2 < NO_; j2++)
                if (j2 < kk)
                    s -= A[i * (i + 1) / 2 + j2] * A[kk * (kk + 1) / 2 + j2];
            A[i * (i + 1) / 2 + kk] = s * rdi[kk];
        }
        float s = A[i * (i + 1) / 2 + i];
#pragma unroll
        for (int j2 = 0; j2 < NO_; j2++)
            if (j2 < i) {
                const float l = A[i * (i + 1) / 2 + j2];
                s -= l * l;
            }
        rdi[i] = rsqrtf(s);
        logdet += __logf(s);
    }

    // forward solve z = L^{-1} e ; quad = |z|^2
    float quad = 0.0f;
    float zv[NO_];
#pragma unroll
    for (int i = 0; i < NO_; i++) {
        float s = e[i];
#pragma unroll
        for (int j2 = 0; j2 < NO_; j2++)
            if (j2 < i) s -= A[i * (i + 1) / 2 + j2] * zv[j2];
        zv[i] = s * rdi[i];
        quad = fmaf(zv[i], zv[i], quad);
    }

    double local = (double)(logdet + quad);

    // block reduction -> one atomicAdd; last block finalizes
    for (int off = 16; off > 0; off >>= 1)
        local += __shfl_down_sync(0xffffffffu, local, off);
    if ((tid & 31) == 0) wsum[tid >> 5] = local;
    __syncthreads();
    if (tid == 0) {
        double s = 0.0;
#pragma unroll
        for (int w = 0; w < 8; w++) s += wsum[w];
        atomicAdd(&g_acc, s);
        __threadfence();
        const unsigned int d = atomicAdd(&g_done, 1u);
        if (d == gridDim.x - 1) {
            __threadfence();
            const double LOG2PI = 1.8378770664093453;
            const double acc = *((volatile double*)&g_acc);
            is_last = true;
            out[0] = (float)(-0.5 * LOG2PI - 0.5 * acc / ((double)NN * TT * NO_));
        }
    }
    (void)is_last;
}

extern "C" void kernel_launch(void* const* d_in, const int* in_sizes, int n_in,
                              void* d_out, int out_size)
{
    const float* Yi    = (const float*)d_in[0];
    const float* Xh    = (const float*)d_in[1];
    const float* Cw    = (const float*)d_in[2];
    const float* Hm    = (const float*)d_in[3];
    const float* mu_w  = (const float*)d_in[4];
    const float* Wi    = (const float*)d_in[5];
    const float* Wh    = (const float*)d_in[6];
    const float* bi    = (const float*)d_in[7];
    const float* bh    = (const float*)d_in[8];
    const float* W_mu  = (const float*)d_in[9];
    const float* b_mu  = (const float*)d_in[10];
    const float* W_var = (const float*)d_in[11];
    const float* b_var = (const float*)d_in[12];
    float* out = (float*)d_out;

    xproj_kernel<<<NN * TT / RPB, GG>>>(Yi, Xh, Wi, bi);
    gru_scan_kernel<<<NN, GG>>>(Wh, bh);
    lik_kernel<<<NN * TT / 256, 256>>>(Yi, Cw, Hm, mu_w, W_mu, b_mu, W_var, b_var, out);
}